// round 4
// baseline (speedup 1.0000x reference)
#include <cuda_runtime.h>

// ---------------------------------------------------------------------------
// CMIAttentionMatrixForAcrobot, restructured:
//   T[j,i]   = sum_n data_q[n,i] * W_lin[j,n]                (phase1 split-K)
//   k[j,m]   = sum_i data_k[j,i] * W_k[m,i] + b_k[m]         (phase1 row-GEMV)
//   nq[m,j]  = sum_i W_q[m,i] * T[j,i] + b_q[m]*slin[j] + b_lin[j]   (phase2 A)
//   kmod     = relu6(k^2 + 2k + nq*(1+|k|))                  (phase2 B)
//   v[j,i]   = sum_m W_q[m,i] * kmod[j,m]                    (phase2 C, W_q from L2)
//   c[j]     = sum_m b_q[m] * kmod[j,m]                      (phase2 partials)
//   out[n,j] = (sum_i data_q[n,i] * v[j,i] + c[j]) / 64      (dot row-GEMV + epiB)
// All hot loops use packed fma.rn.f32x2.
// ---------------------------------------------------------------------------

typedef unsigned long long u64;

#define N_DIM 4096
#define JD 6
#define NSPLIT 128
#define RPS 32
#define CSLABS 8
#define SPLITK_BLOCKS (CSLABS * NSPLIT)   // 1024
#define KSPLIT 8
#define CPK (N_DIM / KSPLIT)              // 512
#define RGX (N_DIM / 8)                   // 512
#define RG_BLOCKS (RGX * KSPLIT)          // 4096
#define P2_BLOCKS 128
#define P2_ROWS 32
#define EPIB_BLOCKS 32

// scratch (static device globals; no allocation)
__device__ float g_Tpart[NSPLIT * JD * N_DIM];
__device__ float g_vpart[P2_BLOCKS * JD * N_DIM];
__device__ float g_T[JD * N_DIM];
__device__ float g_v[JD * N_DIM];
__device__ float g_rgpart[2 * KSPLIT * N_DIM * JD];   // slot0 = k partials, slot1 = dot partials
__device__ float g_cpart[P2_BLOCKS * JD];
__device__ float g_slin[JD];

// ---- packed fp32x2 helpers ------------------------------------------------
__device__ __forceinline__ u64 pk2(float a, float b) {
    u64 r;
    asm("mov.b64 %0, {%1, %2};" : "=l"(r) : "r"(__float_as_uint(a)), "r"(__float_as_uint(b)));
    return r;
}
__device__ __forceinline__ float2 upk(u64 v) {
    unsigned lo, hi;
    asm("mov.b64 {%0, %1}, %2;" : "=r"(lo), "=r"(hi) : "l"(v));
    return make_float2(__uint_as_float(lo), __uint_as_float(hi));
}
__device__ __forceinline__ void fma2(u64& d, u64 a, u64 b) {
    asm("fma.rn.f32x2 %0, %1, %2, %0;" : "+l"(d) : "l"(a), "l"(b));
}
__device__ __forceinline__ void add2(u64& d, u64 a) {
    asm("add.rn.f32x2 %0, %0, %1;" : "+l"(d) : "l"(a));
}

// --------------------------------------------------------------------------
// phase-1 bodies (128-thread blocks)
// --------------------------------------------------------------------------
__device__ __forceinline__ void slin_body(const float* __restrict__ Wlin) {
    const int wid = threadIdx.x >> 5;
    const int lane = threadIdx.x & 31;
    for (int j = wid; j < JD; j += 4) {
        const float4* p = (const float4*)(Wlin + j * N_DIM);
        float s = 0.0f;
        for (int q = lane; q < N_DIM / 4; q += 32) {
            float4 v = p[q];
            s += v.x + v.y + v.z + v.w;
        }
        #pragma unroll
        for (int o = 16; o; o >>= 1) s += __shfl_xor_sync(0xffffffffu, s, o);
        if (lane == 0) g_slin[j] = s;
    }
}

__device__ __forceinline__ void splitk_body(const float* __restrict__ big,
                                            const float* __restrict__ w,
                                            float* __restrict__ part,
                                            int cslab, int split,
                                            float (*ws)[RPS]) {
    const int tid = threadIdx.x;
    const int c0 = cslab * 512 + tid * 4;
    const int r0 = split * RPS;

    for (int idx = tid; idx < JD * RPS; idx += 128) {
        int j = idx / RPS, rr = idx % RPS;
        ws[j][rr] = w[j * N_DIM + r0 + rr];
    }
    __syncthreads();

    u64 acc[JD][2];
    #pragma unroll
    for (int j = 0; j < JD; j++) { acc[j][0] = 0ull; acc[j][1] = 0ull; }

    const ulonglong2* bp = (const ulonglong2*)(big + (size_t)r0 * N_DIM) + (c0 >> 2);
    #pragma unroll 8
    for (int rr = 0; rr < RPS; rr++) {
        ulonglong2 d = bp[(size_t)rr * (N_DIM / 4)];
        #pragma unroll
        for (int j = 0; j < JD; j++) {
            u64 wp = pk2(ws[j][rr], ws[j][rr]);
            fma2(acc[j][0], d.x, wp);
            fma2(acc[j][1], d.y, wp);
        }
    }

    float* p = part + (size_t)split * (JD * N_DIM);
    #pragma unroll
    for (int j = 0; j < JD; j++) {
        float2 a = upk(acc[j][0]), b = upk(acc[j][1]);
        *(float4*)(p + j * N_DIM + c0) = make_float4(a.x, a.y, b.x, b.y);
    }
}

__device__ __forceinline__ void rowgemv_body(const float* __restrict__ big,
                                             const float* __restrict__ S,
                                             float* __restrict__ partbase,
                                             int rowblk, int ks,
                                             ulonglong2 (*ss)[CPK / 4]) {
    const int tid = threadIdx.x;
    const int wid = tid >> 5;
    const int lane = tid & 31;
    const int cbase = ks * CPK;
    const int r0 = rowblk * 8 + wid * 2;

    for (int idx = tid; idx < JD * (CPK / 4); idx += 128) {
        int j = idx >> 7, q = idx & 127;
        ss[j][q] = ((const ulonglong2*)(S + j * N_DIM + cbase))[q];
    }
    __syncthreads();

    u64 a0[JD], a1[JD];
    #pragma unroll
    for (int j = 0; j < JD; j++) { a0[j] = 0ull; a1[j] = 0ull; }

    const ulonglong2* b0 = (const ulonglong2*)(big + (size_t)r0 * N_DIM + cbase);
    const ulonglong2* b1 = (const ulonglong2*)(big + (size_t)(r0 + 1) * N_DIM + cbase);

    #pragma unroll
    for (int it = 0; it < CPK / 128; it++) {
        const int q = it * 32 + lane;
        ulonglong2 m0 = b0[q], m1 = b1[q];
        #pragma unroll
        for (int j = 0; j < JD; j++) {
            ulonglong2 sv = ss[j][q];
            fma2(a0[j], m0.x, sv.x); fma2(a0[j], m0.y, sv.y);
            fma2(a1[j], m1.x, sv.x); fma2(a1[j], m1.y, sv.y);
        }
    }

    #pragma unroll
    for (int j = 0; j < JD; j++) {
        #pragma unroll
        for (int o = 16; o; o >>= 1) {
            add2(a0[j], __shfl_xor_sync(0xffffffffu, a0[j], o));
            add2(a1[j], __shfl_xor_sync(0xffffffffu, a1[j], o));
        }
    }

    if (lane == 0) {
        float* p = partbase + (size_t)ks * (N_DIM * JD);
        #pragma unroll
        for (int j = 0; j < JD; j++) {
            float2 f0 = upk(a0[j]), f1 = upk(a1[j]);
            p[(size_t)r0 * JD + j] = f0.x + f0.y;
            p[(size_t)(r0 + 1) * JD + j] = f1.x + f1.y;
        }
    }
}

// --------------------------------------------------------------------------
// Phase 1: T-splitk (data_q x W_lin) + k-rowgemv (W_k x data_k) + slin.
// --------------------------------------------------------------------------
__global__ void __launch_bounds__(128) phase1_kernel(
        const float* __restrict__ data_q, const float* __restrict__ W_lin,
        const float* __restrict__ W_k,    const float* __restrict__ data_k) {
    __shared__ ulonglong2 ss[JD][CPK / 4];   // 12KB (splitk aliases it as ws)
    const int bid = blockIdx.x;
    if (bid < SPLITK_BLOCKS) {
        splitk_body(data_q, W_lin, g_Tpart, bid >> 7, bid & 127, (float (*)[RPS])ss);
    } else if (bid < SPLITK_BLOCKS + RG_BLOCKS) {
        const int rb = bid - SPLITK_BLOCKS;
        rowgemv_body(W_k, data_k, g_rgpart, rb >> 3, rb & 7, ss);
    } else {
        slin_body(W_lin);
    }
}

// dot pass (data_q x g_v) -> slot 1 partials
__global__ void __launch_bounds__(128) dot_kernel(const float* __restrict__ data_q) {
    __shared__ ulonglong2 ss[JD][CPK / 4];
    rowgemv_body(data_q, g_v, g_rgpart + (size_t)KSPLIT * N_DIM * JD,
                 blockIdx.x, blockIdx.y, ss);
}

// --------------------------------------------------------------------------
// reduce partials: out[idx] = sum_s part[s][idx]. 48 blocks x 128 threads.
// --------------------------------------------------------------------------
__global__ void __launch_bounds__(128) reduce_parts_kernel(int which) {
    const float* __restrict__ part = which ? g_vpart : g_Tpart;
    float* __restrict__ out = which ? g_v : g_T;
    const int idx = blockIdx.x * 128 + threadIdx.x;   // float4 index, 6144 total
    const float4* p4 = (const float4*)part;
    float4 acc = make_float4(0.f, 0.f, 0.f, 0.f);
    #pragma unroll 8
    for (int s = 0; s < NSPLIT; s++) {
        float4 v = p4[(size_t)s * (JD * N_DIM / 4) + idx];
        acc.x += v.x; acc.y += v.y; acc.z += v.z; acc.w += v.w;
    }
    ((float4*)out)[idx] = acc;
}

// --------------------------------------------------------------------------
// Phase 2: fused nq -> kmod -> v over one streaming of W_q (+L2 re-read).
// 128 blocks x 512 threads, 32 rows/block, 8 cols/thread.
// Packed over (j, j+1) pairs: lane of u64 = j parity.
// --------------------------------------------------------------------------
__global__ void __launch_bounds__(512) phase2_kernel(
        const float* __restrict__ Wq,  const float* __restrict__ b_q,
        const float* __restrict__ b_k, const float* __restrict__ b_lin) {
    __shared__ float nqw[16][P2_ROWS][JD];   // [warp][row][j], 12KB
    __shared__ float kmod_s[P2_ROWS][JD];

    const int tid = threadIdx.x;
    const int w = tid >> 5;
    const int lane = tid & 31;
    const int r0 = blockIdx.x * P2_ROWS;
    const int cu = tid * 2;                  // ulonglong2 index of first of 2 (8 cols)

    // T chunk packed by j-pairs: Tp[p][c] = (T[2p][col], T[2p+1][col]), c = 0..7
    u64 Tp[3][8];
    #pragma unroll
    for (int p = 0; p < 3; p++) {
        const float4* e4 = (const float4*)(g_T + (2 * p) * N_DIM);
        const float4* o4 = (const float4*)(g_T + (2 * p + 1) * N_DIM);
        float4 e0 = e4[tid * 2], e1 = e4[tid * 2 + 1];
        float4 o0 = o4[tid * 2], o1 = o4[tid * 2 + 1];
        Tp[p][0] = pk2(e0.x, o0.x); Tp[p][1] = pk2(e0.y, o0.y);
        Tp[p][2] = pk2(e0.z, o0.z); Tp[p][3] = pk2(e0.w, o0.w);
        Tp[p][4] = pk2(e1.x, o1.x); Tp[p][5] = pk2(e1.y, o1.y);
        Tp[p][6] = pk2(e1.z, o1.z); Tp[p][7] = pk2(e1.w, o1.w);
    }

    // ---- Phase A: nq partial dots ----
    const ulonglong2* wrow = (const ulonglong2*)(Wq + (size_t)r0 * N_DIM) + cu;
    #pragma unroll 2
    for (int rr = 0; rr < P2_ROWS; rr++) {
        ulonglong2 m0 = wrow[0], m1 = wrow[1];
        wrow += N_DIM / 4;
        float2 f0 = upk(m0.x), f1 = upk(m0.y), f2 = upk(m1.x), f3 = upk(m1.y);
        u64 mm[8];
        mm[0] = pk2(f0.x, f0.x); mm[1] = pk2(f0.y, f0.y);
        mm[2] = pk2(f1.x, f1.x); mm[3] = pk2(f1.y, f1.y);
        mm[4] = pk2(f2.x, f2.x); mm[5] = pk2(f2.y, f2.y);
        mm[6] = pk2(f3.x, f3.x); mm[7] = pk2(f3.y, f3.y);

        u64 acc[3] = {0ull, 0ull, 0ull};
        #pragma unroll
        for (int p = 0; p < 3; p++)
            #pragma unroll
            for (int c = 0; c < 8; c++)
                fma2(acc[p], mm[c], Tp[p][c]);

        #pragma unroll
        for (int p = 0; p < 3; p++) {
            #pragma unroll
            for (int o = 16; o; o >>= 1)
                add2(acc[p], __shfl_xor_sync(0xffffffffu, acc[p], o));
        }
        if (lane == 0) {
            #pragma unroll
            for (int p = 0; p < 3; p++) {
                float2 f = upk(acc[p]);
                nqw[w][rr][2 * p] = f.x;
                nqw[w][rr][2 * p + 1] = f.y;
            }
        }
    }
    __syncthreads();

    // ---- Phase B: finalize k, nq -> kmod ----
    if (tid < P2_ROWS * JD) {
        const int rr = tid & 31;
        const int j = tid >> 5;
        const int m = r0 + rr;
        float nq = 0.f;
        #pragma unroll
        for (int ww = 0; ww < 16; ww++) nq += nqw[ww][rr][j];
        nq += b_q[m] * g_slin[j] + b_lin[j];
        float kv = 0.f;
        #pragma unroll
        for (int ks = 0; ks < KSPLIT; ks++)
            kv += g_rgpart[(size_t)ks * (N_DIM * JD) + (size_t)m * JD + j];
        kv += b_k[m];
        float x = fmaf(kv, kv, 2.0f * kv) + nq * (1.0f + fabsf(kv));
        kmod_s[rr][j] = fminf(fmaxf(x, 0.0f), 6.0f);
    }
    __syncthreads();

    // ---- Phase C: v partials (re-stream W_q rows from L2) ----
    u64 vp[3][8];
    #pragma unroll
    for (int p = 0; p < 3; p++)
        #pragma unroll
        for (int c = 0; c < 8; c++) vp[p][c] = 0ull;

    wrow = (const ulonglong2*)(Wq + (size_t)r0 * N_DIM) + cu;
    #pragma unroll 2
    for (int rr = 0; rr < P2_ROWS; rr++) {
        ulonglong2 m0 = wrow[0], m1 = wrow[1];
        wrow += N_DIM / 4;
        float2 f0 = upk(m0.x), f1 = upk(m0.y), f2 = upk(m1.x), f3 = upk(m1.y);
        u64 mm[8];
        mm[0] = pk2(f0.x, f0.x); mm[1] = pk2(f0.y, f0.y);
        mm[2] = pk2(f1.x, f1.x); mm[3] = pk2(f1.y, f1.y);
        mm[4] = pk2(f2.x, f2.x); mm[5] = pk2(f2.y, f2.y);
        mm[6] = pk2(f3.x, f3.x); mm[7] = pk2(f3.y, f3.y);

        u64 km[3];
        #pragma unroll
        for (int p = 0; p < 3; p++) km[p] = pk2(kmod_s[rr][2 * p], kmod_s[rr][2 * p + 1]);

        #pragma unroll
        for (int p = 0; p < 3; p++)
            #pragma unroll
            for (int c = 0; c < 8; c++)
                fma2(vp[p][c], mm[c], km[p]);
    }

    // write v partials: g_vpart[block][j][col]
    float* vbase = g_vpart + (size_t)blockIdx.x * (JD * N_DIM);
    #pragma unroll
    for (int p = 0; p < 3; p++) {
        float2 u0 = upk(vp[p][0]), u1 = upk(vp[p][1]), u2 = upk(vp[p][2]), u3 = upk(vp[p][3]);
        float2 u4 = upk(vp[p][4]), u5 = upk(vp[p][5]), u6 = upk(vp[p][6]), u7 = upk(vp[p][7]);
        float4* ev = (float4*)(vbase + (2 * p) * N_DIM) + tid * 2;
        float4* ov = (float4*)(vbase + (2 * p + 1) * N_DIM) + tid * 2;
        ev[0] = make_float4(u0.x, u1.x, u2.x, u3.x);
        ev[1] = make_float4(u4.x, u5.x, u6.x, u7.x);
        ov[0] = make_float4(u0.y, u1.y, u2.y, u3.y);
        ov[1] = make_float4(u4.y, u5.y, u6.y, u7.y);
    }

    // c partials: c[j] = sum_rr b_q[r0+rr] * kmod[rr][j]
    if (tid < JD) {
        float s = 0.f;
        #pragma unroll
        for (int rr = 0; rr < P2_ROWS; rr++)
            s += b_q[r0 + rr] * kmod_s[rr][tid];
        g_cpart[blockIdx.x * JD + tid] = s;
    }
}

// --------------------------------------------------------------------------
// Epilogue B: out[m,j] = (sum_ks dotpart[ks][m][j] + sum_b cpart[b][j]) / 64
// --------------------------------------------------------------------------
__global__ void __launch_bounds__(128) epilogueB_kernel(float* __restrict__ out) {
    const int m = blockIdx.x * 128 + threadIdx.x;

    float acc[JD];
    #pragma unroll
    for (int j = 0; j < JD; j++) acc[j] = 0.f;
    #pragma unroll 4
    for (int b = 0; b < P2_BLOCKS; b++)
        #pragma unroll
        for (int j = 0; j < JD; j++) acc[j] += g_cpart[b * JD + j];

    const float* dp = g_rgpart + (size_t)KSPLIT * (N_DIM * JD);
    #pragma unroll
    for (int ks = 0; ks < KSPLIT; ks++) {
        const float* p = dp + (size_t)ks * (N_DIM * JD) + (size_t)m * JD;
        #pragma unroll
        for (int j = 0; j < JD; j++) acc[j] += p[j];
    }
    #pragma unroll
    for (int j = 0; j < JD; j++)
        out[m * JD + j] = acc[j] * 0.015625f;
}

// --------------------------------------------------------------------------
extern "C" void kernel_launch(void* const* d_in, const int* in_sizes, int n_in,
                              void* d_out, int out_size) {
    const float* data_q = (const float*)d_in[0];   // [4096,4096]
    const float* data_k = (const float*)d_in[1];   // [6,4096]
    const float* W_q    = (const float*)d_in[2];   // [4096,4096]
    const float* b_q    = (const float*)d_in[3];   // [4096]
    const float* W_lin  = (const float*)d_in[4];   // [6,4096]
    const float* b_lin  = (const float*)d_in[5];   // [6]
    const float* W_k    = (const float*)d_in[6];   // [4096,4096]
    const float* b_k    = (const float*)d_in[7];   // [4096]
    float* out = (float*)d_out;                    // [4096,6]

    phase1_kernel<<<SPLITK_BLOCKS + RG_BLOCKS + 1, 128>>>(data_q, W_lin, W_k, data_k);
    reduce_parts_kernel<<<48, 128>>>(0);                         // g_T
    phase2_kernel<<<P2_BLOCKS, 512>>>(W_q, b_q, b_k, b_lin);     // v partials + c partials
    reduce_parts_kernel<<<48, 128>>>(1);                         // g_v
    dot_kernel<<<dim3(RGX, KSPLIT), 128>>>(data_q);              // dot partials
    epilogueB_kernel<<<EPIB_BLOCKS, 128>>>(out);                 // out
}

// round 5
// speedup vs baseline: 1.2767x; 1.2767x over previous
#include <cuda_runtime.h>

// ---------------------------------------------------------------------------
// CMIAttentionMatrixForAcrobot, restructured (atomic column reductions):
//   T[j,i]   = sum_n data_q[n,i] * W_lin[j,n]            (splitk -> REDG into g_T)
//   k[j,m]   = sum_i data_k[j,i] * W_k[m,i] + b_k[m]     (row-GEMV partials slot0)
//   nq[m,j]  = sum_i W_q[m,i] * T[j,i] + b_q[m]*slin[j] + b_lin[j]  (slot1)
//   kmod     = relu6(k^2 + 2k + nq*(1+|k|))              (epilogue A)
//   v[j,i]   = sum_m W_q[m,i] * kmod[j,m]                (splitk -> REDG into g_v)
//   c[j]     = sum_m b_q[m] * kmod[j,m]                  (epilogue A partials)
//   out[n,j] = (sum_i data_q[n,i] * v[j,i] + c[j]) / 64  (row-GEMV slot0 + epi B)
// g_T/g_v rely on zero-init of device globals and are re-zeroed by epilogueB's
// tail each call (invariant preserved across graph replays).
// ---------------------------------------------------------------------------

typedef unsigned long long u64;

#define N_DIM 4096
#define JD 6
#define NSPLIT 64
#define RPS 64                            // rows per split
#define CSLABS 8                          // 512-col slabs
#define SPLITK_BLOCKS (CSLABS * NSPLIT)   // 512
#define KSPLIT 8
#define CPK (N_DIM / KSPLIT)              // 512
#define RGX (N_DIM / 8)                   // 512 row-blocks (8 rows each)
#define RG_BLOCKS (RGX * KSPLIT)          // 4096
#define EPIA_BLOCKS 32
#define EPIB_BLOCKS 32

// scratch (static device globals; zero-initialized at module load)
__device__ float g_T[JD * N_DIM];
__device__ float g_v[JD * N_DIM];
__device__ float g_kmod[JD * N_DIM];
__device__ float g_rgpart[2 * KSPLIT * N_DIM * JD];   // slot0: k then dot; slot1: nq
__device__ float g_cpart[EPIA_BLOCKS * JD];
__device__ float g_slin[JD];

// ---- packed fp32x2 helpers ------------------------------------------------
__device__ __forceinline__ u64 pk2(float a, float b) {
    u64 r;
    asm("mov.b64 %0, {%1, %2};" : "=l"(r) : "r"(__float_as_uint(a)), "r"(__float_as_uint(b)));
    return r;
}
__device__ __forceinline__ float2 upk(u64 v) {
    unsigned lo, hi;
    asm("mov.b64 {%0, %1}, %2;" : "=r"(lo), "=r"(hi) : "l"(v));
    return make_float2(__uint_as_float(lo), __uint_as_float(hi));
}
__device__ __forceinline__ void fma2(u64& d, u64 a, u64 b) {
    asm("fma.rn.f32x2 %0, %1, %2, %0;" : "+l"(d) : "l"(a), "l"(b));
}
__device__ __forceinline__ void add2(u64& d, u64 a) {
    asm("add.rn.f32x2 %0, %0, %1;" : "+l"(d) : "l"(a));
}

// --------------------------------------------------------------------------
// bodies (128-thread blocks)
// --------------------------------------------------------------------------
__device__ __forceinline__ void slin_body(const float* __restrict__ Wlin) {
    const int wid = threadIdx.x >> 5;
    const int lane = threadIdx.x & 31;
    for (int j = wid; j < JD; j += 4) {
        const float4* p = (const float4*)(Wlin + j * N_DIM);
        float s = 0.0f;
        for (int q = lane; q < N_DIM / 4; q += 32) {
            float4 v = p[q];
            s += v.x + v.y + v.z + v.w;
        }
        #pragma unroll
        for (int o = 16; o; o >>= 1) s += __shfl_xor_sync(0xffffffffu, s, o);
        if (lane == 0) g_slin[j] = s;
    }
}

// split-K column reduction with atomic accumulation into out[j*N + i].
// Block covers RPS=64 rows x 512 cols. w[j*N + r] is the small factor.
__device__ __forceinline__ void splitk_body(const float* __restrict__ big,
                                            const float* __restrict__ w,
                                            float* __restrict__ out,
                                            int cslab, int split,
                                            float (*ws)[RPS]) {
    const int tid = threadIdx.x;
    const int c0 = cslab * 512 + tid * 4;
    const int r0 = split * RPS;

    for (int idx = tid; idx < JD * RPS; idx += 128) {
        int j = idx / RPS, rr = idx % RPS;
        ws[j][rr] = w[j * N_DIM + r0 + rr];
    }
    __syncthreads();

    u64 acc[JD][2];
    #pragma unroll
    for (int j = 0; j < JD; j++) { acc[j][0] = 0ull; acc[j][1] = 0ull; }

    const ulonglong2* bp = (const ulonglong2*)(big + (size_t)r0 * N_DIM) + (c0 >> 2);
    #pragma unroll 8
    for (int rr = 0; rr < RPS; rr++) {
        ulonglong2 d = bp[(size_t)rr * (N_DIM / 4)];
        #pragma unroll
        for (int j = 0; j < JD; j++) {
            u64 wp = pk2(ws[j][rr], ws[j][rr]);
            fma2(acc[j][0], d.x, wp);
            fma2(acc[j][1], d.y, wp);
        }
    }

    #pragma unroll
    for (int j = 0; j < JD; j++) {
        float2 a = upk(acc[j][0]), b = upk(acc[j][1]);
        float* o = out + j * N_DIM + c0;
        atomicAdd(o + 0, a.x);
        atomicAdd(o + 1, a.y);
        atomicAdd(o + 2, b.x);
        atomicAdd(o + 3, b.y);
    }
}

// row-GEMV, KSPLIT column splits, 8 rows/block (4 warps x 2 rows).
__device__ __forceinline__ void rowgemv_body(const float* __restrict__ big,
                                             const float* __restrict__ S,
                                             float* __restrict__ partbase,
                                             int rowblk, int ks,
                                             ulonglong2 (*ss)[CPK / 4]) {
    const int tid = threadIdx.x;
    const int wid = tid >> 5;
    const int lane = tid & 31;
    const int cbase = ks * CPK;
    const int r0 = rowblk * 8 + wid * 2;

    for (int idx = tid; idx < JD * (CPK / 4); idx += 128) {
        int j = idx >> 7, q = idx & 127;
        ss[j][q] = ((const ulonglong2*)(S + j * N_DIM + cbase))[q];
    }
    __syncthreads();

    u64 a0[JD], a1[JD];
    #pragma unroll
    for (int j = 0; j < JD; j++) { a0[j] = 0ull; a1[j] = 0ull; }

    const ulonglong2* b0 = (const ulonglong2*)(big + (size_t)r0 * N_DIM + cbase);
    const ulonglong2* b1 = (const ulonglong2*)(big + (size_t)(r0 + 1) * N_DIM + cbase);

    #pragma unroll
    for (int it = 0; it < CPK / 128; it++) {
        const int q = it * 32 + lane;
        ulonglong2 m0 = b0[q], m1 = b1[q];
        #pragma unroll
        for (int j = 0; j < JD; j++) {
            ulonglong2 sv = ss[j][q];
            fma2(a0[j], m0.x, sv.x); fma2(a0[j], m0.y, sv.y);
            fma2(a1[j], m1.x, sv.x); fma2(a1[j], m1.y, sv.y);
        }
    }

    #pragma unroll
    for (int j = 0; j < JD; j++) {
        #pragma unroll
        for (int o = 16; o; o >>= 1) {
            add2(a0[j], __shfl_xor_sync(0xffffffffu, a0[j], o));
            add2(a1[j], __shfl_xor_sync(0xffffffffu, a1[j], o));
        }
    }

    if (lane == 0) {
        float* p = partbase + (size_t)ks * (N_DIM * JD);
        #pragma unroll
        for (int j = 0; j < JD; j++) {
            float2 f0 = upk(a0[j]), f1 = upk(a1[j]);
            p[(size_t)r0 * JD + j] = f0.x + f0.y;
            p[(size_t)(r0 + 1) * JD + j] = f1.x + f1.y;
        }
    }
}

// --------------------------------------------------------------------------
// Phase 1: T-splitk (atomics into g_T) + k-rowgemv (slot0) + slin.
// --------------------------------------------------------------------------
__global__ void __launch_bounds__(128) phase1_kernel(
        const float* __restrict__ data_q, const float* __restrict__ W_lin,
        const float* __restrict__ W_k,    const float* __restrict__ data_k) {
    __shared__ ulonglong2 ss[JD][CPK / 4];   // 12KB (splitk aliases as ws)
    const int bid = blockIdx.x;
    if (bid < SPLITK_BLOCKS) {
        splitk_body(data_q, W_lin, g_T, bid & 7, bid >> 3, (float (*)[RPS])ss);
    } else if (bid < SPLITK_BLOCKS + RG_BLOCKS) {
        const int rb = bid - SPLITK_BLOCKS;
        rowgemv_body(W_k, data_k, g_rgpart, rb >> 3, rb & 7, ss);
    } else {
        slin_body(W_lin);
    }
}

// nq pass: W_q x g_T -> slot1 partials
__global__ void __launch_bounds__(128) nq_kernel(const float* __restrict__ W_q) {
    __shared__ ulonglong2 ss[JD][CPK / 4];
    rowgemv_body(W_q, g_T, g_rgpart + (size_t)KSPLIT * N_DIM * JD,
                 blockIdx.x, blockIdx.y, ss);
}

// v pass: splitk over W_q with w = g_kmod, atomics into g_v
__global__ void __launch_bounds__(128) vsplit_kernel(const float* __restrict__ W_q) {
    __shared__ float ws[JD][RPS];
    splitk_body(W_q, g_kmod, g_v, blockIdx.x, blockIdx.y, ws);
}

// dot pass: data_q x g_v -> slot0 partials (k partials dead by now)
__global__ void __launch_bounds__(128) dot_kernel(const float* __restrict__ data_q) {
    __shared__ ulonglong2 ss[JD][CPK / 4];
    rowgemv_body(data_q, g_v, g_rgpart, blockIdx.x, blockIdx.y, ss);
}

// --------------------------------------------------------------------------
// Epilogue A: finalize k and nq, compute kmod (column-major) + c partials.
// 32 blocks x 128 threads, one row per thread.
// --------------------------------------------------------------------------
__global__ void __launch_bounds__(128) epilogueA_kernel(
        const float* __restrict__ b_k, const float* __restrict__ b_q,
        const float* __restrict__ b_lin) {
    __shared__ float red[JD][128];
    const int tid = threadIdx.x;
    const int m = blockIdx.x * 128 + tid;

    float k[JD], nq[JD];
    #pragma unroll
    for (int j = 0; j < JD; j++) { k[j] = 0.f; nq[j] = 0.f; }

    #pragma unroll
    for (int ks = 0; ks < KSPLIT; ks++) {
        const float* p0 = g_rgpart + ((size_t)ks * N_DIM + m) * JD;
        const float* p1 = g_rgpart + ((size_t)(KSPLIT + ks) * N_DIM + m) * JD;
        #pragma unroll
        for (int j = 0; j < JD; j++) { k[j] += p0[j]; nq[j] += p1[j]; }
    }

    const float bk = b_k[m];
    const float bq = b_q[m];
    float cp[JD];
    #pragma unroll
    for (int j = 0; j < JD; j++) {
        float kv = k[j] + bk;
        float nqv = nq[j] + bq * g_slin[j] + b_lin[j];
        float x = fmaf(kv, kv, 2.0f * kv) + nqv * (1.0f + fabsf(kv));
        float km = fminf(fmaxf(x, 0.0f), 6.0f);
        g_kmod[j * N_DIM + m] = km;
        cp[j] = bq * km;
    }

    #pragma unroll
    for (int j = 0; j < JD; j++) red[j][tid] = cp[j];
    __syncthreads();
    for (int s = 64; s > 0; s >>= 1) {
        if (tid < s) {
            #pragma unroll
            for (int j = 0; j < JD; j++) red[j][tid] += red[j][tid + s];
        }
        __syncthreads();
    }
    if (tid < JD) g_cpart[blockIdx.x * JD + tid] = red[tid][0];
}

// --------------------------------------------------------------------------
// Epilogue B: out[m,j] = (sum_ks dotpart[ks][m][j] + c[j]) / 64.
// Tail: re-zero g_T and g_v for the next call (graph replays).
// --------------------------------------------------------------------------
__global__ void __launch_bounds__(128) epilogueB_kernel(float* __restrict__ out) {
    const int tid = threadIdx.x;
    const int m = blockIdx.x * 128 + tid;

    float acc[JD];
    #pragma unroll
    for (int j = 0; j < JD; j++) acc[j] = 0.f;
    #pragma unroll 4
    for (int b = 0; b < EPIA_BLOCKS; b++)
        #pragma unroll
        for (int j = 0; j < JD; j++) acc[j] += g_cpart[b * JD + j];

    #pragma unroll
    for (int ks = 0; ks < KSPLIT; ks++) {
        const float* p = g_rgpart + ((size_t)ks * N_DIM + m) * JD;
        #pragma unroll
        for (int j = 0; j < JD; j++) acc[j] += p[j];
    }
    #pragma unroll
    for (int j = 0; j < JD; j++)
        out[m * JD + j] = acc[j] * 0.015625f;

    // tail-zero accumulators for the next invocation
    const int gt = blockIdx.x * 128 + tid;               // 4096 threads
    float4* t4 = (float4*)g_T;
    float4* v4 = (float4*)g_v;
    const float4 z = make_float4(0.f, 0.f, 0.f, 0.f);
    #pragma unroll
    for (int idx = gt; idx < JD * N_DIM / 4; idx += EPIB_BLOCKS * 128) {
        t4[idx] = z;
        v4[idx] = z;
    }
}

// --------------------------------------------------------------------------
extern "C" void kernel_launch(void* const* d_in, const int* in_sizes, int n_in,
                              void* d_out, int out_size) {
    const float* data_q = (const float*)d_in[0];   // [4096,4096]
    const float* data_k = (const float*)d_in[1];   // [6,4096]
    const float* W_q    = (const float*)d_in[2];   // [4096,4096]
    const float* b_q    = (const float*)d_in[3];   // [4096]
    const float* W_lin  = (const float*)d_in[4];   // [6,4096]
    const float* b_lin  = (const float*)d_in[5];   // [6]
    const float* W_k    = (const float*)d_in[6];   // [4096,4096]
    const float* b_k    = (const float*)d_in[7];   // [4096]
    float* out = (float*)d_out;                    // [4096,6]

    phase1_kernel<<<SPLITK_BLOCKS + RG_BLOCKS + 1, 128>>>(data_q, W_lin, W_k, data_k);
    nq_kernel<<<dim3(RGX, KSPLIT), 128>>>(W_q);                 // nq partials
    epilogueA_kernel<<<EPIA_BLOCKS, 128>>>(b_k, b_q, b_lin);    // kmod + c partials
    vsplit_kernel<<<dim3(CSLABS, NSPLIT), 128>>>(W_q);          // v (atomic)
    dot_kernel<<<dim3(RGX, KSPLIT), 128>>>(data_q);             // dot partials
    epilogueB_kernel<<<EPIB_BLOCKS, 128>>>(out);                // out + re-zero
}

// round 6
// speedup vs baseline: 1.4139x; 1.1074x over previous
#include <cuda_runtime.h>

// ---------------------------------------------------------------------------
// CMIAttentionMatrixForAcrobot, restructured (vectored-atomic column reductions):
//   T[j,i]   = sum_n data_q[n,i] * W_lin[j,n]            (splitk -> red.v4 into g_T)
//   k[j,m]   = sum_i data_k[j,i] * W_k[m,i] + b_k[m]     (row-GEMV partials slot0)
//   nq[m,j]  = sum_i W_q[m,i] * T[j,i] + b_q[m]*slin[j] + b_lin[j]  (slot1)
//   kmod     = relu6(k^2 + 2k + nq*(1+|k|))              (epilogue A)
//   v[j,i]   = sum_m W_q[m,i] * kmod[j,m]                (splitk -> red.v4 into g_v)
//   c[j]     = sum_m b_q[m] * kmod[j,m]                  (epilogue A partials)
//   out[n,j] = (sum_i data_q[n,i] * v[j,i] + c[j]) / 64  (row-GEMV slot0 + epi B)
// g_T/g_v rely on zero-init of device globals and are re-zeroed by epilogueB's
// tail each call (invariant preserved across graph replays).
// ---------------------------------------------------------------------------

typedef unsigned long long u64;

#define N_DIM 4096
#define JD 6
#define NTHR 256

// T splitk: 64 rows x 1024 cols per block
#define RPS_T 64
#define NSPLIT_T 64
#define SPLITK_T_BLOCKS (4 * NSPLIT_T)    // 256
// v splitk: 32 rows x 1024 cols per block
#define RPS_V 32
#define NSPLIT_V 128
#define SPLITK_V_BLOCKS (4 * NSPLIT_V)    // 512

// row-GEMV: 16 rows x 512 cols per block
#define KSPLIT 8
#define CPK (N_DIM / KSPLIT)              // 512
#define RGROWS 16
#define RGX (N_DIM / RGROWS)              // 256
#define RG_BLOCKS (RGX * KSPLIT)          // 2048

#define EPIA_BLOCKS 32
#define EPIB_BLOCKS 32

// scratch (static device globals; zero-initialized at module load)
__device__ float g_T[JD * N_DIM];
__device__ float g_v[JD * N_DIM];
__device__ float g_kmod[JD * N_DIM];
__device__ float g_rgpart[2 * KSPLIT * N_DIM * JD];   // slot0: k then dot; slot1: nq
__device__ float g_cpart[EPIA_BLOCKS * JD];
__device__ float g_slin[JD];

// ---- packed fp32x2 helpers ------------------------------------------------
__device__ __forceinline__ u64 pk2(float a, float b) {
    u64 r;
    asm("mov.b64 %0, {%1, %2};" : "=l"(r) : "r"(__float_as_uint(a)), "r"(__float_as_uint(b)));
    return r;
}
__device__ __forceinline__ float2 upk(u64 v) {
    unsigned lo, hi;
    asm("mov.b64 {%0, %1}, %2;" : "=r"(lo), "=r"(hi) : "l"(v));
    return make_float2(__uint_as_float(lo), __uint_as_float(hi));
}
__device__ __forceinline__ void fma2(u64& d, u64 a, u64 b) {
    asm("fma.rn.f32x2 %0, %1, %2, %0;" : "+l"(d) : "l"(a), "l"(b));
}
__device__ __forceinline__ void add2(u64& d, u64 a) {
    asm("add.rn.f32x2 %0, %0, %1;" : "+l"(d) : "l"(a));
}
// vectored global float reduction (sm_90+), 4 floats per op
__device__ __forceinline__ void red4(float* gp, float a, float b, float c, float d) {
    asm volatile(
        "{\n\t.reg .u64 p;\n\t"
        "cvta.to.global.u64 p, %0;\n\t"
        "red.global.add.v4.f32 [p], {%1, %2, %3, %4};\n\t}"
        :: "l"(gp), "f"(a), "f"(b), "f"(c), "f"(d) : "memory");
}

// --------------------------------------------------------------------------
// bodies (256-thread blocks)
// --------------------------------------------------------------------------
__device__ __forceinline__ void slin_body(const float* __restrict__ Wlin) {
    const int wid = threadIdx.x >> 5;
    const int lane = threadIdx.x & 31;
    if (wid < JD) {
        const float4* p = (const float4*)(Wlin + wid * N_DIM);
        float s = 0.0f;
        for (int q = lane; q < N_DIM / 4; q += 32) {
            float4 v = p[q];
            s += v.x + v.y + v.z + v.w;
        }
        #pragma unroll
        for (int o = 16; o; o >>= 1) s += __shfl_xor_sync(0xffffffffu, s, o);
        if (lane == 0) g_slin[wid] = s;
    }
}

// split-K column reduction with vectored atomic accumulation into out[j*N + i].
// Block: RPS_ rows x 1024 cols, 256 threads, 4 cols (one float4) per thread.
template<int RPS_>
__device__ __forceinline__ void splitk_body(const float* __restrict__ big,
                                            const float* __restrict__ w,
                                            float* __restrict__ out,
                                            int cslab, int split,
                                            float* ws_raw) {
    float (*ws)[RPS_] = (float (*)[RPS_])ws_raw;
    const int tid = threadIdx.x;
    const int c0 = cslab * 1024 + tid * 4;
    const int r0 = split * RPS_;

    for (int idx = tid; idx < JD * RPS_; idx += NTHR) {
        int j = idx / RPS_, rr = idx % RPS_;
        ws[j][rr] = w[j * N_DIM + r0 + rr];
    }
    __syncthreads();

    u64 acc[JD][2];
    #pragma unroll
    for (int j = 0; j < JD; j++) { acc[j][0] = 0ull; acc[j][1] = 0ull; }

    const ulonglong2* bp = (const ulonglong2*)big + (((size_t)r0 * N_DIM + c0) >> 2);
    #pragma unroll 8
    for (int rr = 0; rr < RPS_; rr++) {
        ulonglong2 d = bp[(size_t)rr * (N_DIM / 4)];
        #pragma unroll
        for (int j = 0; j < JD; j++) {
            u64 wp = pk2(ws[j][rr], ws[j][rr]);
            fma2(acc[j][0], d.x, wp);
            fma2(acc[j][1], d.y, wp);
        }
    }

    #pragma unroll
    for (int j = 0; j < JD; j++) {
        float2 a = upk(acc[j][0]), b = upk(acc[j][1]);
        red4(out + j * N_DIM + c0, a.x, a.y, b.x, b.y);
    }
}

// row-GEMV: 16 rows (8 warps x 2 rows) x CPK cols per block, KSPLIT col splits.
__device__ __forceinline__ void rowgemv_body(const float* __restrict__ big,
                                             const float* __restrict__ S,
                                             float* __restrict__ partbase,
                                             int rowblk, int ks,
                                             ulonglong2 (*ss)[CPK / 4]) {
    const int tid = threadIdx.x;
    const int wid = tid >> 5;
    const int lane = tid & 31;
    const int cbase = ks * CPK;
    const int r0 = rowblk * RGROWS + wid * 2;

    for (int idx = tid; idx < JD * (CPK / 4); idx += NTHR) {
        int j = idx >> 7, q = idx & 127;
        ss[j][q] = ((const ulonglong2*)(S + j * N_DIM + cbase))[q];
    }
    __syncthreads();

    u64 a0[JD], a1[JD];
    #pragma unroll
    for (int j = 0; j < JD; j++) { a0[j] = 0ull; a1[j] = 0ull; }

    const ulonglong2* b0 = (const ulonglong2*)(big + (size_t)r0 * N_DIM + cbase);
    const ulonglong2* b1 = (const ulonglong2*)(big + (size_t)(r0 + 1) * N_DIM + cbase);

    #pragma unroll
    for (int it = 0; it < CPK / 128; it++) {
        const int q = it * 32 + lane;
        ulonglong2 m0 = b0[q], m1 = b1[q];
        #pragma unroll
        for (int j = 0; j < JD; j++) {
            ulonglong2 sv = ss[j][q];
            fma2(a0[j], m0.x, sv.x); fma2(a0[j], m0.y, sv.y);
            fma2(a1[j], m1.x, sv.x); fma2(a1[j], m1.y, sv.y);
        }
    }

    #pragma unroll
    for (int j = 0; j < JD; j++) {
        #pragma unroll
        for (int o = 16; o; o >>= 1) {
            add2(a0[j], __shfl_xor_sync(0xffffffffu, a0[j], o));
            add2(a1[j], __shfl_xor_sync(0xffffffffu, a1[j], o));
        }
    }

    if (lane == 0) {
        float* p = partbase + (size_t)ks * (N_DIM * JD);
        #pragma unroll
        for (int j = 0; j < JD; j++) {
            float2 f0 = upk(a0[j]), f1 = upk(a1[j]);
            p[(size_t)r0 * JD + j] = f0.x + f0.y;
            p[(size_t)(r0 + 1) * JD + j] = f1.x + f1.y;
        }
    }
}

// --------------------------------------------------------------------------
// Phase 1: T-splitk (red.v4 into g_T) + k-rowgemv (slot0) + slin.
// --------------------------------------------------------------------------
__global__ void __launch_bounds__(NTHR) phase1_kernel(
        const float* __restrict__ data_q, const float* __restrict__ W_lin,
        const float* __restrict__ W_k,    const float* __restrict__ data_k) {
    __shared__ ulonglong2 ss[JD][CPK / 4];   // 12KB (splitk aliases as ws)
    const int bid = blockIdx.x;
    if (bid < SPLITK_T_BLOCKS) {
        splitk_body<RPS_T>(data_q, W_lin, g_T, bid & 3, bid >> 2, (float*)ss);
    } else if (bid < SPLITK_T_BLOCKS + RG_BLOCKS) {
        const int rb = bid - SPLITK_T_BLOCKS;
        rowgemv_body(W_k, data_k, g_rgpart, rb >> 3, rb & 7, ss);
    } else {
        slin_body(W_lin);
    }
}

// nq pass: W_q x g_T -> slot1 partials
__global__ void __launch_bounds__(NTHR) nq_kernel(const float* __restrict__ W_q) {
    __shared__ ulonglong2 ss[JD][CPK / 4];
    rowgemv_body(W_q, g_T, g_rgpart + (size_t)KSPLIT * N_DIM * JD,
                 blockIdx.x, blockIdx.y, ss);
}

// v pass: splitk over W_q with w = g_kmod, red.v4 into g_v
__global__ void __launch_bounds__(NTHR) vsplit_kernel(const float* __restrict__ W_q) {
    __shared__ float ws[JD][RPS_V];
    splitk_body<RPS_V>(W_q, g_kmod, g_v, blockIdx.x, blockIdx.y, (float*)ws);
}

// dot pass: data_q x g_v -> slot0 partials (k partials dead by now)
__global__ void __launch_bounds__(NTHR) dot_kernel(const float* __restrict__ data_q) {
    __shared__ ulonglong2 ss[JD][CPK / 4];
    rowgemv_body(data_q, g_v, g_rgpart, blockIdx.x, blockIdx.y, ss);
}

// --------------------------------------------------------------------------
// Epilogue A: finalize k and nq, compute kmod (column-major) + c partials.
// 32 blocks x 128 threads, one row per thread.
// --------------------------------------------------------------------------
__global__ void __launch_bounds__(128) epilogueA_kernel(
        const float* __restrict__ b_k, const float* __restrict__ b_q,
        const float* __restrict__ b_lin) {
    __shared__ float red[JD][128];
    const int tid = threadIdx.x;
    const int m = blockIdx.x * 128 + tid;

    float k[JD], nq[JD];
    #pragma unroll
    for (int j = 0; j < JD; j++) { k[j] = 0.f; nq[j] = 0.f; }

    #pragma unroll
    for (int ks = 0; ks < KSPLIT; ks++) {
        const float* p0 = g_rgpart + ((size_t)ks * N_DIM + m) * JD;
        const float* p1 = g_rgpart + ((size_t)(KSPLIT + ks) * N_DIM + m) * JD;
        #pragma unroll
        for (int j = 0; j < JD; j++) { k[j] += p0[j]; nq[j] += p1[j]; }
    }

    const float bk = b_k[m];
    const float bq = b_q[m];
    float cp[JD];
    #pragma unroll
    for (int j = 0; j < JD; j++) {
        float kv = k[j] + bk;
        float nqv = nq[j] + bq * g_slin[j] + b_lin[j];
        float x = fmaf(kv, kv, 2.0f * kv) + nqv * (1.0f + fabsf(kv));
        float km = fminf(fmaxf(x, 0.0f), 6.0f);
        g_kmod[j * N_DIM + m] = km;
        cp[j] = bq * km;
    }

    #pragma unroll
    for (int j = 0; j < JD; j++) red[j][tid] = cp[j];
    __syncthreads();
    for (int s = 64; s > 0; s >>= 1) {
        if (tid < s) {
            #pragma unroll
            for (int j = 0; j < JD; j++) red[j][tid] += red[j][tid + s];
        }
        __syncthreads();
    }
    if (tid < JD) g_cpart[blockIdx.x * JD + tid] = red[tid][0];
}

// --------------------------------------------------------------------------
// Epilogue B: out[m,j] = (sum_ks dotpart[ks][m][j] + c[j]) / 64.
// Tail: re-zero g_T and g_v for the next call (graph replays).
// --------------------------------------------------------------------------
__global__ void __launch_bounds__(128) epilogueB_kernel(float* __restrict__ out) {
    const int tid = threadIdx.x;
    const int m = blockIdx.x * 128 + tid;

    float acc[JD];
    #pragma unroll
    for (int j = 0; j < JD; j++) acc[j] = 0.f;
    #pragma unroll 4
    for (int b = 0; b < EPIA_BLOCKS; b++)
        #pragma unroll
        for (int j = 0; j < JD; j++) acc[j] += g_cpart[b * JD + j];

    #pragma unroll
    for (int ks = 0; ks < KSPLIT; ks++) {
        const float* p = g_rgpart + ((size_t)ks * N_DIM + m) * JD;
        #pragma unroll
        for (int j = 0; j < JD; j++) acc[j] += p[j];
    }
    #pragma unroll
    for (int j = 0; j < JD; j++)
        out[m * JD + j] = acc[j] * 0.015625f;

    // tail-zero accumulators for the next invocation
    const int gt = blockIdx.x * 128 + tid;               // 4096 threads
    float4* t4 = (float4*)g_T;
    float4* v4 = (float4*)g_v;
    const float4 z = make_float4(0.f, 0.f, 0.f, 0.f);
    #pragma unroll
    for (int idx = gt; idx < JD * N_DIM / 4; idx += EPIB_BLOCKS * 128) {
        t4[idx] = z;
        v4[idx] = z;
    }
}

// --------------------------------------------------------------------------
extern "C" void kernel_launch(void* const* d_in, const int* in_sizes, int n_in,
                              void* d_out, int out_size) {
    const float* data_q = (const float*)d_in[0];   // [4096,4096]
    const float* data_k = (const float*)d_in[1];   // [6,4096]
    const float* W_q    = (const float*)d_in[2];   // [4096,4096]
    const float* b_q    = (const float*)d_in[3];   // [4096]
    const float* W_lin  = (const float*)d_in[4];   // [6,4096]
    const float* b_lin  = (const float*)d_in[5];   // [6]
    const float* W_k    = (const float*)d_in[6];   // [4096,4096]
    const float* b_k    = (const float*)d_in[7];   // [4096]
    float* out = (float*)d_out;                    // [4096,6]

    phase1_kernel<<<SPLITK_T_BLOCKS + RG_BLOCKS + 1, NTHR>>>(data_q, W_lin, W_k, data_k);
    nq_kernel<<<dim3(RGX, KSPLIT), NTHR>>>(W_q);                // nq partials
    epilogueA_kernel<<<EPIA_BLOCKS, 128>>>(b_k, b_q, b_lin);    // kmod + c partials
    vsplit_kernel<<<dim3(4, NSPLIT_V), NTHR>>>(W_q);            // v (red.v4)
    dot_kernel<<<dim3(RGX, KSPLIT), NTHR>>>(data_q);            // dot partials
    epilogueB_kernel<<<EPIB_BLOCKS, 128>>>(out);                // out + re-zero
}